// round 1
// baseline (speedup 1.0000x reference)
#include <cuda_runtime.h>
#include <cuda_bf16.h>

// AP-loss forward. loss = 1 - mean(running-max precision over sorted fg).
// Strategy: reduce O(FG*N) to one O(N log FG) bucketing pass using the
// piecewise-linear structure of clip((l - f)/2 + 0.5, 0, 1):
//   b(f) = #{bg: l >= f+1} + sum_{bg: f-1<l<f+1} (0.5 l + 0.5 - 0.5 f)
// needs only cumulative count/sum of bg logits below each of the 512
// boundary values {f_i - 1} u {f_i + 1}.

#define NFG 256
#define NBOUND 512
#define NBUCKET 513

__device__ unsigned long long g_buckets[NBUCKET];
__device__ float g_fg[NFG];
__device__ int   g_fgcount;
__device__ float g_sf[NFG];       // sorted fg logits
__device__ float g_bounds[NBOUND]; // sorted merged boundaries

// ---------------- K1: zero scratch ----------------
__global__ void zero_kernel() {
    int t = threadIdx.x;
    if (t < NBUCKET) g_buckets[t] = 0ull;
    if (t == NBUCKET) g_fgcount = 0;
}

// ---------------- K2: extract fg logits ----------------
__global__ void extract_kernel(const float* __restrict__ logits,
                               const int* __restrict__ targets, int n) {
    int i = blockIdx.x * blockDim.x + threadIdx.x;
    int stride = gridDim.x * blockDim.x;
    for (; i < n; i += stride) {
        if (targets[i] == 1) {
            int p = atomicAdd(&g_fgcount, 1);
            if (p < NFG) g_fg[p] = logits[i];
        }
    }
}

// ---------------- K3: sort fg + build sorted boundaries ----------------
__device__ __forceinline__ void bitonic_sort(float* a, int n, int tid, int nthreads) {
    for (int k = 2; k <= n; k <<= 1) {
        for (int j = k >> 1; j > 0; j >>= 1) {
            __syncthreads();
            for (int i = tid; i < n; i += nthreads) {
                int ixj = i ^ j;
                if (ixj > i) {
                    bool up = ((i & k) == 0);
                    float x = a[i], y = a[ixj];
                    if (up ? (x > y) : (x < y)) { a[i] = y; a[ixj] = x; }
                }
            }
        }
    }
    __syncthreads();
}

__global__ void sort_kernel() {
    __shared__ float s[NFG];
    __shared__ float b[NBOUND];
    int tid = threadIdx.x;
    if (tid < NFG) s[tid] = g_fg[tid];
    __syncthreads();
    bitonic_sort(s, NFG, tid, blockDim.x);
    if (tid < NFG) {
        g_sf[tid] = s[tid];
        b[tid]        = s[tid] - 1.0f;
        b[tid + NFG]  = s[tid] + 1.0f;
    }
    __syncthreads();
    bitonic_sort(b, NBOUND, tid, blockDim.x);
    if (tid < NBOUND) g_bounds[tid] = b[tid];
}

// ---------------- K4: bucket pass over all logits ----------------
// bucket index = #{boundaries <= l} in [0, 512]. One packed 64-bit shared
// atomic per element: count in bits [42:64), fixed-point (l+8)*2^21 in [0:42).
__global__ void __launch_bounds__(256) bucket_kernel(
        const float* __restrict__ logits,
        const int* __restrict__ targets, int n) {
    __shared__ float sb[NBOUND];
    __shared__ unsigned long long sh[NBUCKET];
    for (int i = threadIdx.x; i < NBOUND; i += blockDim.x) sb[i] = g_bounds[i];
    for (int i = threadIdx.x; i < NBUCKET; i += blockDim.x) sh[i] = 0ull;
    __syncthreads();

    int i = blockIdx.x * blockDim.x + threadIdx.x;
    int stride = gridDim.x * blockDim.x;
    for (; i < n; i += stride) {
        float l = logits[i];
        int tgt = targets[i];
        if (tgt == 0) {
            int lo = 0, hi = NBOUND;
            #pragma unroll 10
            while (lo < hi) {
                int mid = (lo + hi) >> 1;
                if (sb[mid] <= l) lo = mid + 1; else hi = mid;
            }
            unsigned long long pack =
                (1ull << 42) +
                (unsigned long long)__float2uint_rn((l + 8.0f) * 2097152.0f);
            atomicAdd(&sh[lo], pack);
        }
    }
    __syncthreads();
    for (int k = threadIdx.x; k < NBUCKET; k += blockDim.x)
        if (sh[k]) atomicAdd(&g_buckets[k], sh[k]);
}

// ---------------- K5: finalize ----------------
__global__ void final_kernel(int n, float* __restrict__ out) {
    __shared__ int    Cp[NBUCKET];   // inclusive prefix counts
    __shared__ double Sp[NBUCKET];   // inclusive prefix sums of l
    __shared__ float  sb[NBOUND];
    __shared__ float  sf[NFG];
    __shared__ double cur[NFG];
    int tid = threadIdx.x;
    if (tid < NBOUND) sb[tid] = g_bounds[tid];
    if (tid < NFG)    sf[tid] = g_sf[tid];
    __syncthreads();

    if (tid == 0) {
        const double inv = 1.0 / 2097152.0;
        long long c = 0; double s = 0.0;
        for (int k = 0; k < NBUCKET; k++) {
            unsigned long long p = g_buckets[k];
            unsigned long long cnt = p >> 42;
            unsigned long long raw = p & ((1ull << 42) - 1ull);
            c += (long long)cnt;
            s += (double)raw * inv - 8.0 * (double)cnt;
            Cp[k] = (int)c;
            Sp[k] = s;
        }
    }
    __syncthreads();

    int nfg = g_fgcount;
    if (nfg > NFG) nfg = NFG;
    int nbg = n - nfg;

    if (tid < nfg) {
        float f = sf[tid];
        float v1 = f - 1.0f;  // bitwise-identical to boundary built in K3
        float v2 = f + 1.0f;
        // first occurrence of v in sb
        int lo = 0, hi = NBOUND;
        while (lo < hi) { int m = (lo + hi) >> 1; if (sb[m] < v1) lo = m + 1; else hi = m; }
        int j1 = lo;
        lo = 0; hi = NBOUND;
        while (lo < hi) { int m = (lo + hi) >> 1; if (sb[m] < v2) lo = m + 1; else hi = m; }
        int j2 = lo;

        int    C1 = Cp[j1], C2 = Cp[j2];
        double S1 = Sp[j1], S2 = Sp[j2];

        double b = (double)(nbg - C2)
                 + 0.5 * (S2 - S1)
                 + (double)(C2 - C1) * 0.5 * (1.0 - (double)f);

        double a = 0.5;
        #pragma unroll 8
        for (int j = 0; j < NFG; j++) {
            float d = (sf[j] - f) * 0.5f + 0.5f;
            a += (double)fminf(fmaxf(d, 0.0f), 1.0f);
        }
        cur[tid] = a / (a + b);
    }
    __syncthreads();

    if (tid == 0) {
        double mx = 0.0, acc = 0.0;
        for (int i = 0; i < nfg; i++) {
            double c2 = cur[i];
            if (c2 > mx) mx = c2;
            acc += mx;
        }
        int denom = (nfg > 1) ? nfg : 1;
        out[0] = (float)(1.0 - acc / (double)denom);
    }
}

// ---------------- launcher ----------------
extern "C" void kernel_launch(void* const* d_in, const int* in_sizes, int n_in,
                              void* d_out, int out_size) {
    const float* logits  = (const float*)d_in[0];
    const int*   targets = (const int*)d_in[1];
    (void)n_in; (void)out_size;
    float* out = (float*)d_out;
    int n = in_sizes[0];

    zero_kernel<<<1, 544>>>();
    {
        int blocks = (n + 255) / 256;
        if (blocks > 4096) blocks = 4096;
        extract_kernel<<<blocks, 256>>>(logits, targets, n);
    }
    sort_kernel<<<1, 512>>>();
    {
        int blocks = 1184;  // 8 CTAs/SM on 148 SMs
        int maxb = (n + 255) / 256;
        if (blocks > maxb) blocks = maxb;
        bucket_kernel<<<blocks, 256>>>(logits, targets, n);
    }
    final_kernel<<<1, 512>>>(n, out);
}

// round 8
// speedup vs baseline: 1.4065x; 1.4065x over previous
#include <cuda_runtime.h>
#include <cuda_bf16.h>

// AP-loss forward. loss = 1 - mean(running-max precision over sorted fg).
//
// Math: b(f) over background needs only cumulative count C(t) and sum S(t)
// of logits below the 512 boundary values {f_i-1} u {f_i+1}. We bucket ALL
// logits (no targets read in the hot pass) and subtract the exact fg
// contributions in the finalize step.

#define NFG 256
#define NBOUND 512
#define NBUCKET 513
#define NLUT 4096

__device__ unsigned long long g_buckets[NBUCKET];
__device__ float g_fg[NFG];
__device__ int   g_fgcount;
__device__ float g_sf[NFG];          // sorted fg logits
__device__ float g_bounds[NBOUND];   // sorted merged boundaries
__device__ unsigned short g_lut[NLUT];
__device__ float g_bmin, g_scale;

// cell function: monotone non-decreasing in l (consistency is all that matters)
__device__ __forceinline__ int cell_of(float l, float bmin, float scale) {
    int c = (int)floorf((l - bmin) * scale);
    return min(max(c, 0), NLUT - 1);
}

// ---------------- K1: zero scratch ----------------
__global__ void zero_kernel() {
    int t = threadIdx.x;
    if (t < NBUCKET) g_buckets[t] = 0ull;
    if (t == NBUCKET) g_fgcount = 0;
}

// ---------------- K2: extract fg logits (vectorized targets read) ----------------
__global__ void extract_kernel(const float* __restrict__ logits,
                               const int* __restrict__ targets, int n) {
    int n4 = n >> 2;
    int i = blockIdx.x * blockDim.x + threadIdx.x;
    int stride = gridDim.x * blockDim.x;
    const int4* t4 = (const int4*)targets;
    for (; i < n4; i += stride) {
        int4 t = t4[i];
        if (t.x | t.y | t.z | t.w) {
            int base = i << 2;
            if (t.x) { int p = atomicAdd(&g_fgcount, 1); if (p < NFG) g_fg[p] = logits[base + 0]; }
            if (t.y) { int p = atomicAdd(&g_fgcount, 1); if (p < NFG) g_fg[p] = logits[base + 1]; }
            if (t.z) { int p = atomicAdd(&g_fgcount, 1); if (p < NFG) g_fg[p] = logits[base + 2]; }
            if (t.w) { int p = atomicAdd(&g_fgcount, 1); if (p < NFG) g_fg[p] = logits[base + 3]; }
        }
    }
    if (blockIdx.x == 0 && threadIdx.x == 0) {
        for (int k = n4 << 2; k < n; k++)
            if (targets[k]) { int p = atomicAdd(&g_fgcount, 1); if (p < NFG) g_fg[p] = logits[k]; }
    }
}

// ---------------- K3: sort fg, build boundaries + LUT ----------------
__device__ __forceinline__ void bitonic_sort(float* a, int n, int tid, int nthreads) {
    for (int k = 2; k <= n; k <<= 1) {
        for (int j = k >> 1; j > 0; j >>= 1) {
            __syncthreads();
            for (int i = tid; i < n; i += nthreads) {
                int ixj = i ^ j;
                if (ixj > i) {
                    bool up = ((i & k) == 0);
                    float x = a[i], y = a[ixj];
                    if (up ? (x > y) : (x < y)) { a[i] = y; a[ixj] = x; }
                }
            }
        }
    }
    __syncthreads();
}

__global__ void sort_kernel() {
    __shared__ float s[NFG];
    __shared__ float b[NBOUND];
    __shared__ int   bc[NBOUND];   // cell index of each sorted bound
    __shared__ float sh_bmin, sh_scale;
    int tid = threadIdx.x;
    if (tid < NFG) s[tid] = g_fg[tid];
    __syncthreads();
    bitonic_sort(s, NFG, tid, blockDim.x);
    if (tid < NFG) {
        g_sf[tid] = s[tid];
        b[tid]       = s[tid] - 1.0f;
        b[tid + NFG] = s[tid] + 1.0f;
    }
    __syncthreads();
    bitonic_sort(b, NBOUND, tid, blockDim.x);
    if (tid < NBOUND) g_bounds[tid] = b[tid];
    if (tid == 0) {
        float bmin = b[0];
        float bmax = b[NBOUND - 1];
        float range = bmax - bmin;
        if (range < 1e-6f) range = 1e-6f;
        sh_bmin = bmin;
        sh_scale = (float)(NLUT - 1) / range;   // keeps interior cells in range
        g_bmin = sh_bmin; g_scale = sh_scale;
    }
    __syncthreads();
    float bmin = sh_bmin, scale = sh_scale;
    if (tid < NBOUND) bc[tid] = cell_of(b[tid], bmin, scale);
    __syncthreads();
    // LUT[c] = #{bounds with cell < c}  (lower_bound over sorted bc)
    for (int c = tid; c < NLUT; c += blockDim.x) {
        int lo = 0, hi = NBOUND;
        while (lo < hi) { int m = (lo + hi) >> 1; if (bc[m] < c) lo = m + 1; else hi = m; }
        g_lut[c] = (unsigned short)lo;
    }
}

// ---------------- K4: bucket pass over ALL logits ----------------
// bucket index = #{bounds <= l} in [0,512]. Packed 64-bit shared atomic:
// count in bits [42:64), fixed-point (l+8)*2^21 in bits [0:42).
__global__ void __launch_bounds__(256) bucket_kernel(
        const float* __restrict__ logits, int n) {
    __shared__ float sb[NBOUND];
    __shared__ unsigned short slut[NLUT];
    __shared__ unsigned long long sh[NBUCKET];
    for (int i = threadIdx.x; i < NBOUND; i += blockDim.x) sb[i] = g_bounds[i];
    for (int i = threadIdx.x; i < NLUT; i += blockDim.x) slut[i] = g_lut[i];
    for (int i = threadIdx.x; i < NBUCKET; i += blockDim.x) sh[i] = 0ull;
    float bmin = g_bmin, scale = g_scale;
    __syncthreads();

    int n4 = n >> 2;
    int i = blockIdx.x * blockDim.x + threadIdx.x;
    int stride = gridDim.x * blockDim.x;
    const float4* l4p = (const float4*)logits;
    for (; i < n4; i += stride) {
        float4 v = l4p[i];
        float ls[4] = {v.x, v.y, v.z, v.w};
        #pragma unroll
        for (int q = 0; q < 4; q++) {
            float l = ls[q];
            int c = cell_of(l, bmin, scale);
            int idx = slut[c];
            while (idx < NBOUND && sb[idx] <= l) idx++;
            unsigned long long pack =
                (1ull << 42) +
                (unsigned long long)__float2uint_rn((l + 8.0f) * 2097152.0f);
            atomicAdd(&sh[idx], pack);
        }
    }
    if (blockIdx.x == 0 && threadIdx.x == 0) {
        for (int k = n4 << 2; k < n; k++) {
            float l = logits[k];
            int c = cell_of(l, bmin, scale);
            int idx = slut[c];
            while (idx < NBOUND && sb[idx] <= l) idx++;
            unsigned long long pack =
                (1ull << 42) +
                (unsigned long long)__float2uint_rn((l + 8.0f) * 2097152.0f);
            atomicAdd(&sh[idx], pack);
        }
    }
    __syncthreads();
    for (int k = threadIdx.x; k < NBUCKET; k += blockDim.x)
        if (sh[k]) atomicAdd(&g_buckets[k], sh[k]);
}

// ---------------- K5: finalize ----------------
__global__ void final_kernel(int n, float* __restrict__ out) {
    __shared__ int    cnt[NBUCKET];
    __shared__ double sum[NBUCKET];
    __shared__ int    Cp[NBUCKET];
    __shared__ double Sp[NBUCKET];
    __shared__ float  sb[NBOUND];
    __shared__ float  sf[NFG];
    __shared__ double sfp[NFG + 1];  // exclusive prefix sums of sorted fg
    __shared__ double cur[NFG];
    int tid = threadIdx.x;

    // parallel decode of the global buckets (fixes the serial-LDG bottleneck)
    if (tid < NBUCKET) {
        unsigned long long p = g_buckets[tid];
        unsigned long long c = p >> 42;
        unsigned long long raw = p & ((1ull << 42) - 1ull);
        cnt[tid] = (int)c;
        sum[tid] = (double)raw * (1.0 / 2097152.0) - 8.0 * (double)c;
    }
    if (tid < NBOUND) sb[tid] = g_bounds[tid];
    if (tid < NFG)    sf[tid] = g_sf[tid];
    __syncthreads();

    if (tid == 0) {
        long long c = 0; double s = 0.0;
        for (int k = 0; k < NBUCKET; k++) {
            c += cnt[k]; s += sum[k];
            Cp[k] = (int)c; Sp[k] = s;
        }
    } else if (tid == 32) {
        double s = 0.0;
        for (int j = 0; j < NFG; j++) { sfp[j] = s; s += (double)sf[j]; }
        sfp[NFG] = s;
    }
    __syncthreads();

    int nfg = g_fgcount;
    if (nfg > NFG) nfg = NFG;
    int nbg = n - nfg;

    if (tid < nfg) {
        float f = sf[tid];
        float v1 = f - 1.0f;   // bitwise-identical to the K3 boundary values
        float v2 = f + 1.0f;
        // first occurrence of v in sb
        int lo = 0, hi = NBOUND;
        while (lo < hi) { int m = (lo + hi) >> 1; if (sb[m] < v1) lo = m + 1; else hi = m; }
        int j1 = lo;
        lo = 0; hi = NBOUND;
        while (lo < hi) { int m = (lo + hi) >> 1; if (sb[m] < v2) lo = m + 1; else hi = m; }
        int j2 = lo;

        // ALL-logits cumulative count/sum below v1, v2
        int    C1 = Cp[j1], C2 = Cp[j2];
        double S1 = Sp[j1], S2 = Sp[j2];

        // fg cumulative count/sum below v1, v2 (exact, same float compares)
        lo = 0; hi = nfg;
        while (lo < hi) { int m = (lo + hi) >> 1; if (sf[m] < v1) lo = m + 1; else hi = m; }
        int F1 = lo;
        lo = 0; hi = nfg;
        while (lo < hi) { int m = (lo + hi) >> 1; if (sf[m] < v2) lo = m + 1; else hi = m; }
        int F2 = lo;
        double FS1 = sfp[F1], FS2 = sfp[F2];

        double Cb1 = (double)(C1 - F1), Cb2 = (double)(C2 - F2);
        double Sb1 = S1 - FS1,          Sb2 = S2 - FS2;

        double b = ((double)nbg - Cb2)
                 + 0.5 * (Sb2 - Sb1)
                 + (Cb2 - Cb1) * 0.5 * (1.0 - (double)f);

        double a = 0.5;
        #pragma unroll 8
        for (int j = 0; j < NFG; j++) {
            float d = (sf[j] - f) * 0.5f + 0.5f;
            a += (double)fminf(fmaxf(d, 0.0f), 1.0f);
        }
        cur[tid] = a / (a + b);
    }
    __syncthreads();

    if (tid == 0) {
        double mx = 0.0, acc = 0.0;
        for (int i = 0; i < nfg; i++) {
            double c2 = cur[i];
            if (c2 > mx) mx = c2;
            acc += mx;
        }
        int denom = (nfg > 1) ? nfg : 1;
        out[0] = (float)(1.0 - acc / (double)denom);
    }
}

// ---------------- launcher ----------------
extern "C" void kernel_launch(void* const* d_in, const int* in_sizes, int n_in,
                              void* d_out, int out_size) {
    const float* logits  = (const float*)d_in[0];
    const int*   targets = (const int*)d_in[1];
    (void)n_in; (void)out_size;
    float* out = (float*)d_out;
    int n = in_sizes[0];

    zero_kernel<<<1, 544>>>();
    {
        int blocks = ((n >> 2) + 255) / 256;
        if (blocks > 2368) blocks = 2368;
        if (blocks < 1) blocks = 1;
        extract_kernel<<<blocks, 256>>>(logits, targets, n);
    }
    sort_kernel<<<1, 512>>>();
    {
        int blocks = 1184;  // 8 CTAs/SM on 148 SMs
        int maxb = ((n >> 2) + 255) / 256;
        if (maxb < 1) maxb = 1;
        if (blocks > maxb) blocks = maxb;
        bucket_kernel<<<blocks, 256>>>(logits, n);
    }
    final_kernel<<<1, 544>>>(n, out);
}

// round 9
// speedup vs baseline: 3.3805x; 2.4036x over previous
#include <cuda_runtime.h>
#include <cuda_bf16.h>

// AP-loss forward, 2-kernel structure with last-CTA-done pattern.
// KA: extract fg logits; last CTA sorts fg, builds sorted boundaries + LUT +
//     fg prefix sums.
// KB: bucket all logits into 513 boundary-interval buckets (packed u64 shared
//     atomics); last CTA does a parallel scan over buckets, closed-form a/b per
//     fg threshold, prefix-max precision, loss. Then re-zeroes all scratch so
//     every kernel_launch call starts from identical state (graph-replay safe;
//     globals are zero-initialized at module load for the first call).

#define NFG 256
#define NBOUND 512
#define NBUCKET 513
#define NLUT 4096
#define MASK42 ((1ull << 42) - 1ull)

__device__ unsigned long long g_buckets[NBUCKET];   // zero-init
__device__ float g_fg[NFG];
__device__ int   g_fgcount;                          // zero-init
__device__ int   g_nfg;
__device__ float g_sf[NFG];
__device__ float g_bounds[NBOUND];
__device__ unsigned short g_lut[NLUT];
__device__ float g_bmin, g_scale;
__device__ double g_sfp[NFG + 1];
__device__ unsigned int g_doneA;                     // zero-init
__device__ unsigned int g_doneB;                     // zero-init

__device__ __forceinline__ int cell_of(float l, float bmin, float scale) {
    int c = (int)floorf((l - bmin) * scale);
    return min(max(c, 0), NLUT - 1);
}

__device__ __forceinline__ void bitonic_sort(float* a, int n, int tid, int nthreads) {
    for (int k = 2; k <= n; k <<= 1) {
        for (int j = k >> 1; j > 0; j >>= 1) {
            __syncthreads();
            for (int i = tid; i < n; i += nthreads) {
                int ixj = i ^ j;
                if (ixj > i) {
                    bool up = ((i & k) == 0);
                    float x = a[i], y = a[ixj];
                    if (up ? (x > y) : (x < y)) { a[i] = y; a[ixj] = x; }
                }
            }
        }
    }
    __syncthreads();
}

// lower_bound over shared float array
__device__ __forceinline__ int lbound(const float* a, int n, float v) {
    int lo = 0, hi = n;
    while (lo < hi) { int m = (lo + hi) >> 1; if (a[m] < v) lo = m + 1; else hi = m; }
    return lo;
}

// ================= KA: extract + prep =================
__global__ void __launch_bounds__(256) extract_prep_kernel(
        const float* __restrict__ logits, const int* __restrict__ targets, int n) {
    int n4 = n >> 2;
    {
        int i = blockIdx.x * blockDim.x + threadIdx.x;
        int stride = gridDim.x * blockDim.x;
        const int4* t4 = (const int4*)targets;
        for (; i < n4; i += stride) {
            int4 t = t4[i];
            if (t.x | t.y | t.z | t.w) {
                int base = i << 2;
                if (t.x) { int p = atomicAdd(&g_fgcount, 1); if (p < NFG) g_fg[p] = logits[base + 0]; }
                if (t.y) { int p = atomicAdd(&g_fgcount, 1); if (p < NFG) g_fg[p] = logits[base + 1]; }
                if (t.z) { int p = atomicAdd(&g_fgcount, 1); if (p < NFG) g_fg[p] = logits[base + 2]; }
                if (t.w) { int p = atomicAdd(&g_fgcount, 1); if (p < NFG) g_fg[p] = logits[base + 3]; }
            }
        }
        if (blockIdx.x == 0 && threadIdx.x == 0) {
            for (int k = n4 << 2; k < n; k++)
                if (targets[k]) { int p = atomicAdd(&g_fgcount, 1); if (p < NFG) g_fg[p] = logits[k]; }
        }
    }
    __threadfence();
    __shared__ bool amLast;
    if (threadIdx.x == 0)
        amLast = (atomicAdd(&g_doneA, 1u) == gridDim.x - 1);
    __syncthreads();
    if (!amLast) return;

    // -------- last CTA (256 threads): sort + bounds + LUT + fg prefix --------
    __shared__ float s[NFG];
    __shared__ float b[NBOUND];
    __shared__ int   bc[NBOUND];
    __shared__ float sh_bmin, sh_scale;
    __shared__ double warpS[8];
    int tid = threadIdx.x;
    int lane = tid & 31, wid = tid >> 5;

    int nfg = atomicAdd(&g_fgcount, 0);
    if (nfg > NFG) nfg = NFG;

    s[tid] = (tid < nfg) ? __ldcg(&g_fg[tid]) : 3.0e38f;   // pad with +inf
    __syncthreads();
    bitonic_sort(s, NFG, tid, 256);
    g_sf[tid] = s[tid];
    {
        bool real = (tid < nfg);
        float fv = s[tid];
        b[tid]       = real ? fv - 1.0f : 3.0e38f;
        b[tid + NFG] = real ? fv + 1.0f : 3.0e38f;
    }
    __syncthreads();
    bitonic_sort(b, NBOUND, tid, 256);
    g_bounds[tid] = b[tid];
    g_bounds[tid + NFG] = b[tid + NFG];
    if (tid == 0) {
        int nb = 2 * nfg;
        float bmin = (nb > 0) ? b[0] : 0.0f;
        float bmax = (nb > 0) ? b[nb - 1] : 1.0f;
        float range = bmax - bmin;
        if (range < 1e-6f) range = 1e-6f;
        sh_bmin = bmin;
        sh_scale = (float)(NLUT - 1) / range;
        g_bmin = bmin; g_scale = sh_scale;
        g_nfg = nfg;
    }
    __syncthreads();
    {
        float bmin = sh_bmin, scale = sh_scale;
        bc[tid]       = cell_of(b[tid], bmin, scale);
        bc[tid + NFG] = cell_of(b[tid + NFG], bmin, scale);
    }
    __syncthreads();
    // LUT[c] = #{bounds with cell < c}
    for (int c = tid; c < NLUT; c += 256) {
        int lo = 0, hi = NBOUND;
        while (lo < hi) { int m = (lo + hi) >> 1; if (bc[m] < c) lo = m + 1; else hi = m; }
        g_lut[c] = (unsigned short)lo;
    }
    // fg prefix sums (block shfl scan over 256 doubles)
    {
        double val = (tid < nfg) ? (double)s[tid] : 0.0;
        double x = val;
        #pragma unroll
        for (int o = 1; o < 32; o <<= 1) {
            double t = __shfl_up_sync(0xffffffffu, x, o);
            if (lane >= o) x += t;
        }
        if (lane == 31) warpS[wid] = x;
        __syncthreads();
        if (wid == 0) {
            double w = (lane < 8) ? warpS[lane] : 0.0;
            #pragma unroll
            for (int o = 1; o < 8; o <<= 1) {
                double t = __shfl_up_sync(0xffffffffu, w, o);
                if (lane >= o) w += t;
            }
            if (lane < 8) warpS[lane] = w;
        }
        __syncthreads();
        double incl = x + ((wid > 0) ? warpS[wid - 1] : 0.0);
        g_sfp[tid] = incl - val;          // exclusive prefix
        if (tid == 255) g_sfp[NFG] = incl;
    }
}

// ================= KB: bucket + finalize =================
// shared layout (14344 B), phase 1:
//   [0,2048)      sb    float[512]
//   [2048,10240)  slut  u16[4096]
//   [10240,14344) sh    u64[513]
// phase 2 (last CTA only, reuses [2048,14344); sb kept):
//   [2048,6152)   Sp    double[513]
//   [6152,8204)   Cp    int[513]
//   [8204,9228)   sf    float[256]
//   [9232,11288)  sfp   double[257]
//   [11288,13336) cur   double[256]
__global__ void __launch_bounds__(256) bucket_final_kernel(
        const float* __restrict__ logits, int n, float* __restrict__ out) {
    __shared__ alignas(16) unsigned char smem_raw[14344];
    __shared__ bool amLast;
    __shared__ double warpS[8];
    __shared__ long long warpC[8];
    __shared__ double warpB[8];

    float* sb = (float*)smem_raw;
    unsigned short* slut = (unsigned short*)(smem_raw + 2048);
    unsigned long long* sh = (unsigned long long*)(smem_raw + 10240);

    int tid = threadIdx.x;
    for (int i = tid; i < NBOUND; i += 256) sb[i] = g_bounds[i];
    for (int i = tid; i < NLUT; i += 256) slut[i] = g_lut[i];
    for (int i = tid; i < NBUCKET; i += 256) sh[i] = 0ull;
    float bmin = g_bmin, scale = g_scale;
    __syncthreads();

    int n4 = n >> 2;
    {
        int i = blockIdx.x * blockDim.x + tid;
        int stride = gridDim.x * blockDim.x;
        const float4* l4p = (const float4*)logits;
        for (; i < n4; i += stride) {
            float4 v = l4p[i];
            float ls[4] = {v.x, v.y, v.z, v.w};
            #pragma unroll
            for (int q = 0; q < 4; q++) {
                float l = ls[q];
                int c = cell_of(l, bmin, scale);
                int idx = slut[c];
                while (idx < NBOUND && sb[idx] <= l) idx++;
                unsigned long long pack =
                    (1ull << 42) +
                    (unsigned long long)__float2uint_rn((l + 8.0f) * 2097152.0f);
                atomicAdd(&sh[idx], pack);
            }
        }
        if (blockIdx.x == 0 && tid == 0) {
            for (int k = n4 << 2; k < n; k++) {
                float l = logits[k];
                int c = cell_of(l, bmin, scale);
                int idx = slut[c];
                while (idx < NBOUND && sb[idx] <= l) idx++;
                unsigned long long pack =
                    (1ull << 42) +
                    (unsigned long long)__float2uint_rn((l + 8.0f) * 2097152.0f);
                atomicAdd(&sh[idx], pack);
            }
        }
    }
    __syncthreads();
    for (int k = tid; k < NBUCKET; k += 256)
        if (sh[k]) atomicAdd(&g_buckets[k], sh[k]);
    __threadfence();
    if (tid == 0)
        amLast = (atomicAdd(&g_doneB, 1u) == gridDim.x - 1);
    __syncthreads();
    if (!amLast) return;

    // -------- last CTA: finalize (256 threads) --------
    double* Sp  = (double*)(smem_raw + 2048);
    int*    Cp  = (int*)(smem_raw + 6152);
    float*  sf  = (float*)(smem_raw + 8204);
    double* sfp = (double*)(smem_raw + 9232);
    double* cur = (double*)(smem_raw + 11288);
    int lane = tid & 31, wid = tid >> 5;

    // decode buckets (2 per thread; thread 255 takes 3) + local sums
    int k0 = 2 * tid;
    int kend = (tid == 255) ? NBUCKET : k0 + 2;
    long long cL = 0; double sL = 0.0;
    for (int k = k0; k < kend; k++) {
        unsigned long long p = __ldcg(&g_buckets[k]);
        long long c = (long long)(p >> 42);
        double sd = (double)(p & MASK42) * (1.0 / 2097152.0) - 8.0 * (double)c;
        Cp[k] = (int)c;      // temp per-bucket value
        Sp[k] = sd;
        cL += c; sL += sd;
    }
    // block inclusive scan of (cL, sL)
    {
        long long xc = cL; double xs = sL;
        #pragma unroll
        for (int o = 1; o < 32; o <<= 1) {
            long long tc = __shfl_up_sync(0xffffffffu, xc, o);
            double    ts = __shfl_up_sync(0xffffffffu, xs, o);
            if (lane >= o) { xc += tc; xs += ts; }
        }
        if (lane == 31) { warpC[wid] = xc; warpS[wid] = xs; }
        __syncthreads();
        if (wid == 0) {
            long long wc = (lane < 8) ? warpC[lane] : 0ll;
            double    ws = (lane < 8) ? warpS[lane] : 0.0;
            #pragma unroll
            for (int o = 1; o < 8; o <<= 1) {
                long long tc = __shfl_up_sync(0xffffffffu, wc, o);
                double    ts = __shfl_up_sync(0xffffffffu, ws, o);
                if (lane >= o) { wc += tc; ws += ts; }
            }
            if (lane < 8) { warpC[lane] = wc; warpS[lane] = ws; }
        }
        __syncthreads();
        long long inclC = xc + ((wid > 0) ? warpC[wid - 1] : 0ll);
        double    inclS = xs + ((wid > 0) ? warpS[wid - 1] : 0.0);
        long long rc = inclC - cL; double rs = inclS - sL;   // exclusive start
        for (int k = k0; k < kend; k++) {
            rc += Cp[k]; rs += Sp[k];
            Cp[k] = (int)rc; Sp[k] = rs;                      // inclusive prefixes
        }
    }
    int nfg = g_nfg;
    sf[tid]  = g_sf[tid];
    sfp[tid] = g_sfp[tid];
    if (tid == 0) sfp[NFG] = g_sfp[NFG];
    __syncthreads();

    int nbg = n - nfg;
    if (tid < nfg) {
        float f = sf[tid];
        float v1 = f - 1.0f;   // bitwise-identical to KA boundary values
        float v2 = f + 1.0f;
        int j1 = lbound(sb, NBOUND, v1);
        int j2 = lbound(sb, NBOUND, v2);
        int    C1 = Cp[j1], C2 = Cp[j2];
        double S1 = Sp[j1], S2 = Sp[j2];
        int F1 = lbound(sf, nfg, v1);
        int F2 = lbound(sf, nfg, v2);
        double FS1 = sfp[F1], FS2 = sfp[F2];

        double Cb1 = (double)(C1 - F1), Cb2 = (double)(C2 - F2);
        double Sb1 = S1 - FS1,          Sb2 = S2 - FS2;
        double bb = ((double)nbg - Cb2) + 0.5 * (Sb2 - Sb1)
                  + (Cb2 - Cb1) * 0.5 * (1.0 - (double)f);
        // closed-form a over fg (same segment decomposition, includes self 0.5)
        double aa = 0.5 + (double)(nfg - F2) + 0.5 * (FS2 - FS1)
                  + (double)(F2 - F1) * 0.5 * (1.0 - (double)f);
        cur[tid] = aa / (aa + bb);
    }
    __syncthreads();

    // prefix-max of cur, then sum of prefix-max over first nfg
    {
        double v = (tid < nfg) ? cur[tid] : -1.0;
        double x = v;
        #pragma unroll
        for (int o = 1; o < 32; o <<= 1) {
            double t = __shfl_up_sync(0xffffffffu, x, o);
            if (lane >= o) x = fmax(x, t);
        }
        if (lane == 31) warpS[wid] = x;
        __syncthreads();
        if (wid == 0) {
            double w = (lane < 8) ? warpS[lane] : -1.0;
            #pragma unroll
            for (int o = 1; o < 8; o <<= 1) {
                double t = __shfl_up_sync(0xffffffffu, w, o);
                if (lane >= o) w = fmax(w, t);
            }
            if (lane < 8) warpS[lane] = w;
        }
        __syncthreads();
        double pm = (wid > 0) ? fmax(x, warpS[wid - 1]) : x;
        double contrib = (tid < nfg) ? pm : 0.0;
        // block sum reduce
        #pragma unroll
        for (int o = 16; o > 0; o >>= 1)
            contrib += __shfl_down_sync(0xffffffffu, contrib, o);
        if (lane == 0) warpB[wid] = contrib;
        __syncthreads();
        if (tid == 0) {
            double acc = 0.0;
            for (int w = 0; w < 8; w++) acc += warpB[w];
            int denom = (nfg > 1) ? nfg : 1;
            out[0] = (float)(1.0 - acc / (double)denom);
        }
    }

    // -------- re-zero all scratch for the next (graph-replayed) call --------
    for (int k = tid; k < NBUCKET; k += 256) g_buckets[k] = 0ull;
    if (tid == 0) { g_fgcount = 0; g_doneA = 0; g_doneB = 0; }
}

// ---------------- launcher ----------------
extern "C" void kernel_launch(void* const* d_in, const int* in_sizes, int n_in,
                              void* d_out, int out_size) {
    const float* logits  = (const float*)d_in[0];
    const int*   targets = (const int*)d_in[1];
    (void)n_in; (void)out_size;
    float* out = (float*)d_out;
    int n = in_sizes[0];

    int n4 = n >> 2;
    int maxb = (n4 + 255) / 256;
    if (maxb < 1) maxb = 1;

    int blocksA = maxb < 1184 ? maxb : 1184;
    extract_prep_kernel<<<blocksA, 256>>>(logits, targets, n);

    int blocksB = maxb < 1184 ? maxb : 1184;
    bucket_final_kernel<<<blocksB, 256>>>(logits, n, out);
}

// round 10
// speedup vs baseline: 4.1294x; 1.2215x over previous
#include <cuda_runtime.h>
#include <cuda_bf16.h>

// AP-loss forward — single fused kernel with software phase barriers.
// Grid is capped at 592 = 148 SMs x 4 CTAs and __launch_bounds__(256,4)
// guarantees full residency, so intra-kernel spin barriers cannot deadlock.
// Phase 1: all CTAs extract fg logits (targets pass).
// Phase P: LAST-ARRIVING CTA sorts fg (bitonic 256), builds the 512 sorted
//          boundaries by stable MERGE of the sorted {f-1} and {f+1} arrays,
//          builds the 4096-cell LUT and fg prefix sums, then releases a flag.
// Phase 2: all CTAs bucket every logit into 513 boundary intervals with one
//          packed u64 shared atomic per element; per-CTA flush to global.
// Phase F: last CTA decodes buckets with a parallel scan, computes closed-form
//          a(f), b(f) per threshold, prefix-max precision, loss; re-zeroes all
//          scratch so every graph replay starts from identical state.

#define NFG 256
#define NBOUND 512
#define NBUCKET 513
#define NLUT 4096
#define MASK42 ((1ull << 42) - 1ull)

__device__ unsigned long long g_buckets[NBUCKET];   // zero-init at load
__device__ float g_fg[NFG];
__device__ int   g_fgcount;                          // zero-init
__device__ int   g_nfg;
__device__ float g_sf[NFG];
__device__ float g_bounds[NBOUND];
__device__ unsigned short g_lut[NLUT];
__device__ float g_bmin, g_scale;
__device__ double g_sfp[NFG + 1];
__device__ unsigned int g_doneA;                     // zero-init
__device__ unsigned int g_doneB;                     // zero-init
__device__ unsigned int g_prepDone;                  // zero-init

__device__ __forceinline__ int cell_of(float l, float bmin, float scale) {
    int c = (int)floorf((l - bmin) * scale);
    return min(max(c, 0), NLUT - 1);
}

__device__ __forceinline__ void bitonic_sort256(float* a, int tid) {
    for (int k = 2; k <= 256; k <<= 1) {
        for (int j = k >> 1; j > 0; j >>= 1) {
            __syncthreads();
            int ixj = tid ^ j;
            if (ixj > tid) {
                bool up = ((tid & k) == 0);
                float x = a[tid], y = a[ixj];
                if (up ? (x > y) : (x < y)) { a[tid] = y; a[ixj] = x; }
            }
        }
    }
    __syncthreads();
}

__device__ __forceinline__ int lboundf(const float* a, int n, float v) {
    int lo = 0, hi = n;
    while (lo < hi) { int m = (lo + hi) >> 1; if (a[m] < v) lo = m + 1; else hi = m; }
    return lo;
}
__device__ __forceinline__ int uboundf(const float* a, int n, float v) {
    int lo = 0, hi = n;
    while (lo < hi) { int m = (lo + hi) >> 1; if (a[m] <= v) lo = m + 1; else hi = m; }
    return lo;
}

// shared overlays on one 14344-byte buffer:
// prep:    s f32[256]@0 | b1 f32[256]@1024 | b2 f32[256]@2048 | bm f32[512]@3072 | bc i32[512]@5120
// bucket:  sb f32[512]@0 | slut u16[4096]@2048 | sh u64[513]@10240
// final:   sb kept @0 | Sp f64[513]@2048 | Cp i32[513]@6152 | sf f32[256]@8204 | sfp f64[257]@9232 | cur f64[256]@11288
__global__ void __launch_bounds__(256, 4) aploss_fused_kernel(
        const float* __restrict__ logits, const int* __restrict__ targets,
        int n, float* __restrict__ out) {
    __shared__ alignas(16) unsigned char smem_raw[14344];
    __shared__ bool amLast;
    __shared__ float sh_bmin, sh_scale;
    __shared__ double warpS[8];
    __shared__ long long warpC[8];
    __shared__ double warpB[8];

    int tid = threadIdx.x;
    int lane = tid & 31, wid = tid >> 5;
    int n4 = n >> 2;

    // ================= phase 1: extract =================
    {
        int i = blockIdx.x * 256 + tid;
        int stride = gridDim.x * 256;
        const int4* t4 = (const int4*)targets;
        for (; i < n4; i += stride) {
            int4 t = t4[i];
            if (t.x | t.y | t.z | t.w) {
                int base = i << 2;
                if (t.x) { int p = atomicAdd(&g_fgcount, 1); if (p < NFG) g_fg[p] = logits[base + 0]; }
                if (t.y) { int p = atomicAdd(&g_fgcount, 1); if (p < NFG) g_fg[p] = logits[base + 1]; }
                if (t.z) { int p = atomicAdd(&g_fgcount, 1); if (p < NFG) g_fg[p] = logits[base + 2]; }
                if (t.w) { int p = atomicAdd(&g_fgcount, 1); if (p < NFG) g_fg[p] = logits[base + 3]; }
            }
        }
        if (blockIdx.x == 0 && tid == 0) {
            for (int k = n4 << 2; k < n; k++)
                if (targets[k]) { int p = atomicAdd(&g_fgcount, 1); if (p < NFG) g_fg[p] = logits[k]; }
        }
    }
    __threadfence();
    if (tid == 0) amLast = (atomicAdd(&g_doneA, 1u) == gridDim.x - 1);
    __syncthreads();

    // ================= phase P: prep (last-arriving CTA only) =================
    if (amLast) {
        float* s  = (float*)smem_raw;
        float* b1 = (float*)(smem_raw + 1024);
        float* b2 = (float*)(smem_raw + 2048);
        float* bm = (float*)(smem_raw + 3072);
        int*   bc = (int*)(smem_raw + 5120);

        int nfg = g_fgcount;
        if (nfg > NFG) nfg = NFG;
        s[tid] = (tid < nfg) ? __ldcg(&g_fg[tid]) : 3.0e38f;
        __syncthreads();
        bitonic_sort256(s, tid);
        g_sf[tid] = s[tid];
        bool real = (tid < nfg);
        float fv = s[tid];
        float v1 = real ? fv - 1.0f : 3.0e38f;
        float v2 = real ? fv + 1.0f : 3.0e38f;
        b1[tid] = v1; b2[tid] = v2;
        __syncthreads();
        // stable merge of sorted b1, b2 into bm[512]
        int p1 = tid + lboundf(b2, NFG, v1);   // # b2 strictly less
        int p2 = tid + uboundf(b1, NFG, v2);   // # b1 less-or-equal
        bm[p1] = v1;
        bm[p2] = v2;
        __syncthreads();
        g_bounds[tid]       = bm[tid];
        g_bounds[tid + NFG] = bm[tid + NFG];
        if (tid == 0) {
            int nb = 2 * nfg;
            float bmin = (nb > 0) ? bm[0] : 0.0f;
            float bmax = (nb > 0) ? bm[nb - 1] : 1.0f;
            float range = bmax - bmin;
            if (range < 1e-6f) range = 1e-6f;
            sh_bmin = bmin; sh_scale = (float)(NLUT - 1) / range;
            g_bmin = bmin; g_scale = sh_scale; g_nfg = nfg;
        }
        __syncthreads();
        bc[tid]       = cell_of(bm[tid], sh_bmin, sh_scale);
        bc[tid + NFG] = cell_of(bm[tid + NFG], sh_bmin, sh_scale);
        __syncthreads();
        // LUT[c] = #{bounds with cell < c}
        #pragma unroll
        for (int c = tid; c < NLUT; c += 256) {
            int lo = 0, hi = NBOUND;
            while (lo < hi) { int m = (lo + hi) >> 1; if (bc[m] < c) lo = m + 1; else hi = m; }
            g_lut[c] = (unsigned short)lo;
        }
        // fg exclusive prefix sums via block shfl scan
        {
            double val = (tid < nfg) ? (double)s[tid] : 0.0;
            double x = val;
            #pragma unroll
            for (int o = 1; o < 32; o <<= 1) {
                double t = __shfl_up_sync(0xffffffffu, x, o);
                if (lane >= o) x += t;
            }
            if (lane == 31) warpS[wid] = x;
            __syncthreads();
            if (wid == 0) {
                double w = (lane < 8) ? warpS[lane] : 0.0;
                #pragma unroll
                for (int o = 1; o < 8; o <<= 1) {
                    double t = __shfl_up_sync(0xffffffffu, w, o);
                    if (lane >= o) w += t;
                }
                if (lane < 8) warpS[lane] = w;
            }
            __syncthreads();
            double incl = x + ((wid > 0) ? warpS[wid - 1] : 0.0);
            g_sfp[tid] = incl - val;
            if (tid == 255) g_sfp[NFG] = incl;
        }
        // release: every thread fences its own writes, then one thread flags
        __threadfence();
        __syncthreads();
        if (tid == 0) atomicExch(&g_prepDone, 1u);
    } else {
        if (tid == 0) {
            volatile unsigned int* f = &g_prepDone;
            while (*f == 0u) __nanosleep(128);
        }
        __syncthreads();
    }

    // ================= phase 2: bucket =================
    float* sb = (float*)smem_raw;
    unsigned short* slut = (unsigned short*)(smem_raw + 2048);
    unsigned long long* sh = (unsigned long long*)(smem_raw + 10240);
    __syncthreads();   // smem overlay switch
    for (int i = tid; i < NBOUND; i += 256) sb[i] = __ldcg(&g_bounds[i]);
    for (int i = tid; i < NLUT; i += 256) slut[i] = __ldcg(&g_lut[i]);
    for (int i = tid; i < NBUCKET; i += 256) sh[i] = 0ull;
    float bmin = __ldcg(&g_bmin), scale = __ldcg(&g_scale);
    __syncthreads();

    {
        int i = blockIdx.x * 256 + tid;
        int stride = gridDim.x * 256;
        const float4* l4p = (const float4*)logits;
        for (; i < n4; i += stride) {
            float4 v = l4p[i];
            float ls[4] = {v.x, v.y, v.z, v.w};
            #pragma unroll
            for (int q = 0; q < 4; q++) {
                float l = ls[q];
                int c = cell_of(l, bmin, scale);
                int idx = slut[c];
                while (idx < NBOUND && sb[idx] <= l) idx++;
                unsigned long long pack =
                    (1ull << 42) +
                    (unsigned long long)__float2uint_rn((l + 8.0f) * 2097152.0f);
                atomicAdd(&sh[idx], pack);
            }
        }
        if (blockIdx.x == 0 && tid == 0) {
            for (int k = n4 << 2; k < n; k++) {
                float l = logits[k];
                int c = cell_of(l, bmin, scale);
                int idx = slut[c];
                while (idx < NBOUND && sb[idx] <= l) idx++;
                unsigned long long pack =
                    (1ull << 42) +
                    (unsigned long long)__float2uint_rn((l + 8.0f) * 2097152.0f);
                atomicAdd(&sh[idx], pack);
            }
        }
    }
    __syncthreads();
    for (int k = tid; k < NBUCKET; k += 256)
        if (sh[k]) atomicAdd(&g_buckets[k], sh[k]);
    __threadfence();
    if (tid == 0) amLast = (atomicAdd(&g_doneB, 1u) == gridDim.x - 1);
    __syncthreads();
    if (!amLast) return;

    // ================= phase F: finalize (last CTA) =================
    double* Sp  = (double*)(smem_raw + 2048);
    int*    Cp  = (int*)(smem_raw + 6152);
    float*  sf  = (float*)(smem_raw + 8204);
    double* sfp = (double*)(smem_raw + 9232);
    double* cur = (double*)(smem_raw + 11288);

    // decode buckets (2/thread; thread 255 takes 3) + block scan of (count,sum)
    int k0 = 2 * tid;
    int kend = (tid == 255) ? NBUCKET : k0 + 2;
    long long cL = 0; double sL = 0.0;
    for (int k = k0; k < kend; k++) {
        unsigned long long p = __ldcg(&g_buckets[k]);
        long long c = (long long)(p >> 42);
        double sd = (double)(p & MASK42) * (1.0 / 2097152.0) - 8.0 * (double)c;
        Cp[k] = (int)c; Sp[k] = sd;
        cL += c; sL += sd;
    }
    {
        long long xc = cL; double xs = sL;
        #pragma unroll
        for (int o = 1; o < 32; o <<= 1) {
            long long tc = __shfl_up_sync(0xffffffffu, xc, o);
            double    ts = __shfl_up_sync(0xffffffffu, xs, o);
            if (lane >= o) { xc += tc; xs += ts; }
        }
        if (lane == 31) { warpC[wid] = xc; warpS[wid] = xs; }
        __syncthreads();
        if (wid == 0) {
            long long wc = (lane < 8) ? warpC[lane] : 0ll;
            double    ws = (lane < 8) ? warpS[lane] : 0.0;
            #pragma unroll
            for (int o = 1; o < 8; o <<= 1) {
                long long tc = __shfl_up_sync(0xffffffffu, wc, o);
                double    ts = __shfl_up_sync(0xffffffffu, ws, o);
                if (lane >= o) { wc += tc; ws += ts; }
            }
            if (lane < 8) { warpC[lane] = wc; warpS[lane] = ws; }
        }
        __syncthreads();
        long long inclC = xc + ((wid > 0) ? warpC[wid - 1] : 0ll);
        double    inclS = xs + ((wid > 0) ? warpS[wid - 1] : 0.0);
        long long rc = inclC - cL; double rs = inclS - sL;
        for (int k = k0; k < kend; k++) {
            rc += Cp[k]; rs += Sp[k];
            Cp[k] = (int)rc; Sp[k] = rs;          // inclusive prefixes
        }
    }
    int nfg = __ldcg(&g_nfg);
    sf[tid]  = __ldcg(&g_sf[tid]);
    sfp[tid] = __ldcg(&g_sfp[tid]);
    if (tid == 0) sfp[NFG] = __ldcg(&g_sfp[NFG]);
    __syncthreads();

    int nbg = n - nfg;
    if (tid < nfg) {
        float f = sf[tid];
        float v1 = f - 1.0f;   // bitwise-identical to prep boundary values
        float v2 = f + 1.0f;
        int j1 = lboundf(sb, NBOUND, v1);
        int j2 = lboundf(sb, NBOUND, v2);
        int    C1 = Cp[j1], C2 = Cp[j2];
        double S1 = Sp[j1], S2 = Sp[j2];
        int F1 = lboundf(sf, nfg, v1);
        int F2 = lboundf(sf, nfg, v2);
        double FS1 = sfp[F1], FS2 = sfp[F2];

        double Cb1 = (double)(C1 - F1), Cb2 = (double)(C2 - F2);
        double Sb1 = S1 - FS1,          Sb2 = S2 - FS2;
        double bb = ((double)nbg - Cb2) + 0.5 * (Sb2 - Sb1)
                  + (Cb2 - Cb1) * 0.5 * (1.0 - (double)f);
        double aa = 0.5 + (double)(nfg - F2) + 0.5 * (FS2 - FS1)
                  + (double)(F2 - F1) * 0.5 * (1.0 - (double)f);
        cur[tid] = aa / (aa + bb);
    }
    __syncthreads();

    // prefix-max + sum
    {
        double v = (tid < nfg) ? cur[tid] : -1.0;
        double x = v;
        #pragma unroll
        for (int o = 1; o < 32; o <<= 1) {
            double t = __shfl_up_sync(0xffffffffu, x, o);
            if (lane >= o) x = fmax(x, t);
        }
        if (lane == 31) warpS[wid] = x;
        __syncthreads();
        if (wid == 0) {
            double w = (lane < 8) ? warpS[lane] : -1.0;
            #pragma unroll
            for (int o = 1; o < 8; o <<= 1) {
                double t = __shfl_up_sync(0xffffffffu, w, o);
                if (lane >= o) w = fmax(w, t);
            }
            if (lane < 8) warpS[lane] = w;
        }
        __syncthreads();
        double pm = (wid > 0) ? fmax(x, warpS[wid - 1]) : x;
        double contrib = (tid < nfg) ? pm : 0.0;
        #pragma unroll
        for (int o = 16; o > 0; o >>= 1)
            contrib += __shfl_down_sync(0xffffffffu, contrib, o);
        if (lane == 0) warpB[wid] = contrib;
        __syncthreads();
        if (tid == 0) {
            double acc = 0.0;
            for (int w = 0; w < 8; w++) acc += warpB[w];
            int denom = (nfg > 1) ? nfg : 1;
            out[0] = (float)(1.0 - acc / (double)denom);
        }
    }

    // re-zero all scratch for the next graph replay
    for (int k = tid; k < NBUCKET; k += 256) g_buckets[k] = 0ull;
    if (tid == 0) { g_fgcount = 0; g_doneA = 0; g_doneB = 0; g_prepDone = 0; }
}

// ---------------- launcher ----------------
extern "C" void kernel_launch(void* const* d_in, const int* in_sizes, int n_in,
                              void* d_out, int out_size) {
    const float* logits  = (const float*)d_in[0];
    const int*   targets = (const int*)d_in[1];
    (void)n_in; (void)out_size;
    float* out = (float*)d_out;
    int n = in_sizes[0];

    int n4 = n >> 2;
    int maxb = (n4 + 255) / 256;
    if (maxb < 1) maxb = 1;
    int blocks = maxb < 592 ? maxb : 592;   // 148 SMs x 4 CTAs: full residency
    aploss_fused_kernel<<<blocks, 256>>>(logits, targets, n, out);
}

// round 12
// speedup vs baseline: 4.2955x; 1.0402x over previous
#include <cuda_runtime.h>
#include <cuda_bf16.h>

// AP-loss forward — single fused kernel with software phase barriers.
// Grid capped at 740 = 148 SMs x 5 CTAs; __launch_bounds__(256,5) guarantees
// full residency, so intra-kernel spin barriers cannot deadlock.
// Phase 1: all CTAs extract fg logits (targets pass).
// Phase P: last-arriving CTA sorts fg, merge-builds the 512 sorted boundaries,
//          range-fills the 4096-cell LUT (bit15 = "boundary in this cell"),
//          builds fg prefix sums, releases a flag.
// Phase 2: all CTAs bucket every logit (packed u64 shared atomic); the LUT
//          flag skips the sb scan for ~87.5% of elements.
// Phase F: last CTA parallel-scans buckets, closed-form a(f), b(f), prefix-max
//          precision, loss; re-zeroes scratch for graph replay.

#define NFG 256
#define NBOUND 512
#define NBUCKET 513
#define NLUT 4096
#define MASK42 ((1ull << 42) - 1ull)
#define LUT_FLAG 0x8000
#define LUT_IDX  0x3FF

__device__ unsigned long long g_buckets[NBUCKET];   // zero-init at load
__device__ float g_fg[NFG];
__device__ int   g_fgcount;                          // zero-init
__device__ int   g_nfg;
__device__ float g_sf[NFG];
__device__ float g_bounds[NBOUND];
__device__ unsigned short g_lut[NLUT];
__device__ float g_bmin, g_scale;
__device__ double g_sfp[NFG + 1];
__device__ unsigned int g_doneA;                     // zero-init
__device__ unsigned int g_doneB;                     // zero-init
__device__ unsigned int g_prepDone;                  // zero-init

__device__ __forceinline__ int cell_of(float l, float bmin, float scale) {
    int c = (int)floorf((l - bmin) * scale);
    return min(max(c, 0), NLUT - 1);
}

__device__ __forceinline__ void bitonic_sort256(float* a, int tid) {
    for (int k = 2; k <= 256; k <<= 1) {
        for (int j = k >> 1; j > 0; j >>= 1) {
            __syncthreads();
            int ixj = tid ^ j;
            if (ixj > tid) {
                bool up = ((tid & k) == 0);
                float x = a[tid], y = a[ixj];
                if (up ? (x > y) : (x < y)) { a[tid] = y; a[ixj] = x; }
            }
        }
    }
    __syncthreads();
}

__device__ __forceinline__ int lboundf(const float* a, int n, float v) {
    int lo = 0, hi = n;
    while (lo < hi) { int m = (lo + hi) >> 1; if (a[m] < v) lo = m + 1; else hi = m; }
    return lo;
}
__device__ __forceinline__ int uboundf(const float* a, int n, float v) {
    int lo = 0, hi = n;
    while (lo < hi) { int m = (lo + hi) >> 1; if (a[m] <= v) lo = m + 1; else hi = m; }
    return lo;
}

// shared overlays on one 14344-byte buffer:
// prep:    s f32[256]@0 | b1 f32[256]@1024 | b2 f32[256]@2048 | bm f32[512]@3072 | bc i32[512]@5120
// bucket:  sb f32[512]@0 | slut u16[4096]@2048 | sh u64[513]@10240
// final:   sb kept @0 | Sp f64[513]@2048 | Cp i32[513]@6152 | sf f32[256]@8204 | sfp f64[257]@9232 | cur f64[256]@11288
__global__ void __launch_bounds__(256, 5) aploss_fused_kernel(
        const float* __restrict__ logits, const int* __restrict__ targets,
        int n, float* __restrict__ out) {
    __shared__ alignas(16) unsigned char smem_raw[14344];
    __shared__ bool amLast;
    __shared__ float sh_bmin, sh_scale;
    __shared__ double warpS[8];
    __shared__ long long warpC[8];
    __shared__ double warpB[8];

    int tid = threadIdx.x;
    int lane = tid & 31, wid = tid >> 5;
    int n4 = n >> 2;

    // ================= phase 1: extract =================
    {
        int i = blockIdx.x * 256 + tid;
        int stride = gridDim.x * 256;
        const int4* t4 = (const int4*)targets;
        for (; i < n4; i += stride) {
            int4 t = t4[i];
            if (t.x | t.y | t.z | t.w) {
                int base = i << 2;
                if (t.x) { int p = atomicAdd(&g_fgcount, 1); if (p < NFG) g_fg[p] = logits[base + 0]; }
                if (t.y) { int p = atomicAdd(&g_fgcount, 1); if (p < NFG) g_fg[p] = logits[base + 1]; }
                if (t.z) { int p = atomicAdd(&g_fgcount, 1); if (p < NFG) g_fg[p] = logits[base + 2]; }
                if (t.w) { int p = atomicAdd(&g_fgcount, 1); if (p < NFG) g_fg[p] = logits[base + 3]; }
            }
        }
        if (blockIdx.x == 0 && tid == 0) {
            for (int k = n4 << 2; k < n; k++)
                if (targets[k]) { int p = atomicAdd(&g_fgcount, 1); if (p < NFG) g_fg[p] = logits[k]; }
        }
    }
    __threadfence();
    if (tid == 0) amLast = (atomicAdd(&g_doneA, 1u) == gridDim.x - 1);
    __syncthreads();

    // ================= phase P: prep (last-arriving CTA only) =================
    if (amLast) {
        float* s  = (float*)smem_raw;
        float* b1 = (float*)(smem_raw + 1024);
        float* b2 = (float*)(smem_raw + 2048);
        float* bm = (float*)(smem_raw + 3072);
        int*   bc = (int*)(smem_raw + 5120);

        int nfg = g_fgcount;
        if (nfg > NFG) nfg = NFG;
        s[tid] = (tid < nfg) ? __ldcg(&g_fg[tid]) : 3.0e38f;
        __syncthreads();
        bitonic_sort256(s, tid);
        g_sf[tid] = s[tid];
        bool real = (tid < nfg);
        float fv = s[tid];
        float v1 = real ? fv - 1.0f : 3.0e38f;
        float v2 = real ? fv + 1.0f : 3.0e38f;
        b1[tid] = v1; b2[tid] = v2;
        __syncthreads();
        // stable merge of sorted b1, b2 into bm[512]
        int p1 = tid + lboundf(b2, NFG, v1);
        int p2 = tid + uboundf(b1, NFG, v2);
        bm[p1] = v1;
        bm[p2] = v2;
        __syncthreads();
        g_bounds[tid]       = bm[tid];
        g_bounds[tid + NFG] = bm[tid + NFG];
        if (tid == 0) {
            int nb = 2 * nfg;
            float bmin = (nb > 0) ? bm[0] : 0.0f;
            float bmax = (nb > 0) ? bm[nb - 1] : 1.0f;
            float range = bmax - bmin;
            if (range < 1e-6f) range = 1e-6f;
            sh_bmin = bmin; sh_scale = (float)(NLUT - 1) / range;
            g_bmin = bmin; g_scale = sh_scale; g_nfg = nfg;
        }
        __syncthreads();
        bc[tid]       = cell_of(bm[tid], sh_bmin, sh_scale);
        bc[tid + NFG] = cell_of(bm[tid + NFG], sh_bmin, sh_scale);
        __syncthreads();
        // range-fill LUT: bound i owns cells (bc[i-1], bc[i]]. Interior cells get
        // idx=i (no boundary in cell => exact answer); cell bc[i] gets i|FLAG.
        #pragma unroll
        for (int ii = 0; ii < 2; ii++) {
            int i = tid + ii * 256;
            int lo = (i == 0) ? -1 : bc[i - 1];
            int hi = bc[i];
            for (int c = lo + 1; c < hi; c++) g_lut[c] = (unsigned short)i;
            if (hi > lo) g_lut[hi] = (unsigned short)(i | LUT_FLAG);
        }
        {
            int last = bc[NBOUND - 1];
            for (int c = last + 1 + tid; c < NLUT; c += 256)
                g_lut[c] = (unsigned short)NBOUND;
        }
        // fg exclusive prefix sums via block shfl scan
        {
            double val = (tid < nfg) ? (double)s[tid] : 0.0;
            double x = val;
            #pragma unroll
            for (int o = 1; o < 32; o <<= 1) {
                double t = __shfl_up_sync(0xffffffffu, x, o);
                if (lane >= o) x += t;
            }
            if (lane == 31) warpS[wid] = x;
            __syncthreads();
            if (wid == 0) {
                double w = (lane < 8) ? warpS[lane] : 0.0;
                #pragma unroll
                for (int o = 1; o < 8; o <<= 1) {
                    double t = __shfl_up_sync(0xffffffffu, w, o);
                    if (lane >= o) w += t;
                }
                if (lane < 8) warpS[lane] = w;
            }
            __syncthreads();
            double incl = x + ((wid > 0) ? warpS[wid - 1] : 0.0);
            g_sfp[tid] = incl - val;
            if (tid == 255) g_sfp[NFG] = incl;
        }
        __threadfence();
        __syncthreads();
        if (tid == 0) atomicExch(&g_prepDone, 1u);
    } else {
        if (tid == 0) {
            volatile unsigned int* f = &g_prepDone;
            while (*f == 0u) __nanosleep(128);
        }
        __syncthreads();
    }

    // ================= phase 2: bucket =================
    float* sb = (float*)smem_raw;
    unsigned short* slut = (unsigned short*)(smem_raw + 2048);
    unsigned long long* sh = (unsigned long long*)(smem_raw + 10240);
    __syncthreads();   // smem overlay switch
    for (int i = tid; i < NBOUND; i += 256) sb[i] = __ldcg(&g_bounds[i]);
    for (int i = tid; i < NLUT; i += 256) slut[i] = __ldcg(&g_lut[i]);
    for (int i = tid; i < NBUCKET; i += 256) sh[i] = 0ull;
    float bmin = __ldcg(&g_bmin), scale = __ldcg(&g_scale);
    __syncthreads();

    {
        int i = blockIdx.x * 256 + tid;
        int stride = gridDim.x * 256;
        const float4* l4p = (const float4*)logits;
        for (; i < n4; i += stride) {
            float4 v = l4p[i];
            float ls[4] = {v.x, v.y, v.z, v.w};
            #pragma unroll
            for (int q = 0; q < 4; q++) {
                float l = ls[q];
                int c = cell_of(l, bmin, scale);
                unsigned int e = slut[c];
                int idx = e & LUT_IDX;
                if (e & LUT_FLAG) {
                    while (idx < NBOUND && sb[idx] <= l) idx++;
                }
                unsigned long long pack =
                    (1ull << 42) +
                    (unsigned long long)__float2uint_rn((l + 8.0f) * 2097152.0f);
                atomicAdd(&sh[idx], pack);
            }
        }
        if (blockIdx.x == 0 && tid == 0) {
            for (int k = n4 << 2; k < n; k++) {
                float l = logits[k];
                int c = cell_of(l, bmin, scale);
                unsigned int e = slut[c];
                int idx = e & LUT_IDX;
                if (e & LUT_FLAG) {
                    while (idx < NBOUND && sb[idx] <= l) idx++;
                }
                unsigned long long pack =
                    (1ull << 42) +
                    (unsigned long long)__float2uint_rn((l + 8.0f) * 2097152.0f);
                atomicAdd(&sh[idx], pack);
            }
        }
    }
    __syncthreads();
    for (int k = tid; k < NBUCKET; k += 256)
        if (sh[k]) atomicAdd(&g_buckets[k], sh[k]);
    __threadfence();
    if (tid == 0) amLast = (atomicAdd(&g_doneB, 1u) == gridDim.x - 1);
    __syncthreads();
    if (!amLast) return;

    // ================= phase F: finalize (last CTA) =================
    double* Sp  = (double*)(smem_raw + 2048);
    int*    Cp  = (int*)(smem_raw + 6152);
    float*  sf  = (float*)(smem_raw + 8204);
    double* sfp = (double*)(smem_raw + 9232);
    double* cur = (double*)(smem_raw + 11288);

    int k0 = 2 * tid;
    int kend = (tid == 255) ? NBUCKET : k0 + 2;
    long long cL = 0; double sL = 0.0;
    for (int k = k0; k < kend; k++) {
        unsigned long long p = __ldcg(&g_buckets[k]);
        long long c = (long long)(p >> 42);
        double sd = (double)(p & MASK42) * (1.0 / 2097152.0) - 8.0 * (double)c;
        Cp[k] = (int)c; Sp[k] = sd;
        cL += c; sL += sd;
    }
    {
        long long xc = cL; double xs = sL;
        #pragma unroll
        for (int o = 1; o < 32; o <<= 1) {
            long long tc = __shfl_up_sync(0xffffffffu, xc, o);
            double    ts = __shfl_up_sync(0xffffffffu, xs, o);
            if (lane >= o) { xc += tc; xs += ts; }
        }
        if (lane == 31) { warpC[wid] = xc; warpS[wid] = xs; }
        __syncthreads();
        if (wid == 0) {
            long long wc = (lane < 8) ? warpC[lane] : 0ll;
            double    ws = (lane < 8) ? warpS[lane] : 0.0;
            #pragma unroll
            for (int o = 1; o < 8; o <<= 1) {
                long long tc = __shfl_up_sync(0xffffffffu, wc, o);
                double    ts = __shfl_up_sync(0xffffffffu, ws, o);
                if (lane >= o) { wc += tc; ws += ts; }
            }
            if (lane < 8) { warpC[lane] = wc; warpS[lane] = ws; }
        }
        __syncthreads();
        long long inclC = xc + ((wid > 0) ? warpC[wid - 1] : 0ll);
        double    inclS = xs + ((wid > 0) ? warpS[wid - 1] : 0.0);
        long long rc = inclC - cL; double rs = inclS - sL;
        for (int k = k0; k < kend; k++) {
            rc += Cp[k]; rs += Sp[k];
            Cp[k] = (int)rc; Sp[k] = rs;          // inclusive prefixes
        }
    }
    int nfg = __ldcg(&g_nfg);
    sf[tid]  = __ldcg(&g_sf[tid]);
    sfp[tid] = __ldcg(&g_sfp[tid]);
    if (tid == 0) sfp[NFG] = __ldcg(&g_sfp[NFG]);
    __syncthreads();

    int nbg = n - nfg;
    if (tid < nfg) {
        float f = sf[tid];
        float v1 = f - 1.0f;   // bitwise-identical to prep boundary values
        float v2 = f + 1.0f;
        int j1 = lboundf(sb, NBOUND, v1);
        int j2 = lboundf(sb, NBOUND, v2);
        int    C1 = Cp[j1], C2 = Cp[j2];
        double S1 = Sp[j1], S2 = Sp[j2];
        int F1 = lboundf(sf, nfg, v1);
        int F2 = lboundf(sf, nfg, v2);
        double FS1 = sfp[F1], FS2 = sfp[F2];

        double Cb1 = (double)(C1 - F1), Cb2 = (double)(C2 - F2);
        double Sb1 = S1 - FS1,          Sb2 = S2 - FS2;
        double bb = ((double)nbg - Cb2) + 0.5 * (Sb2 - Sb1)
                  + (Cb2 - Cb1) * 0.5 * (1.0 - (double)f);
        double aa = 0.5 + (double)(nfg - F2) + 0.5 * (FS2 - FS1)
                  + (double)(F2 - F1) * 0.5 * (1.0 - (double)f);
        cur[tid] = aa / (aa + bb);
    }
    __syncthreads();

    {
        double v = (tid < nfg) ? cur[tid] : -1.0;
        double x = v;
        #pragma unroll
        for (int o = 1; o < 32; o <<= 1) {
            double t = __shfl_up_sync(0xffffffffu, x, o);
            if (lane >= o) x = fmax(x, t);
        }
        if (lane == 31) warpS[wid] = x;
        __syncthreads();
        if (wid == 0) {
            double w = (lane < 8) ? warpS[lane] : -1.0;
            #pragma unroll
            for (int o = 1; o < 8; o <<= 1) {
                double t = __shfl_up_sync(0xffffffffu, w, o);
                if (lane >= o) w = fmax(w, t);
            }
            if (lane < 8) warpS[lane] = w;
        }
        __syncthreads();
        double pm = (wid > 0) ? fmax(x, warpS[wid - 1]) : x;
        double contrib = (tid < nfg) ? pm : 0.0;
        #pragma unroll
        for (int o = 16; o > 0; o >>= 1)
            contrib += __shfl_down_sync(0xffffffffu, contrib, o);
        if (lane == 0) warpB[wid] = contrib;
        __syncthreads();
        if (tid == 0) {
            double acc = 0.0;
            for (int w = 0; w < 8; w++) acc += warpB[w];
            int denom = (nfg > 1) ? nfg : 1;
            out[0] = (float)(1.0 - acc / (double)denom);
        }
    }

    // re-zero all scratch for the next graph replay
    for (int k = tid; k < NBUCKET; k += 256) g_buckets[k] = 0ull;
    if (tid == 0) { g_fgcount = 0; g_doneA = 0; g_doneB = 0; g_prepDone = 0; }
}

// ---------------- launcher ----------------
extern "C" void kernel_launch(void* const* d_in, const int* in_sizes, int n_in,
                              void* d_out, int out_size) {
    const float* logits  = (const float*)d_in[0];
    const int*   targets = (const int*)d_in[1];
    (void)n_in; (void)out_size;
    float* out = (float*)d_out;
    int n = in_sizes[0];

    int n4 = n >> 2;
    int maxb = (n4 + 255) / 256;
    if (maxb < 1) maxb = 1;
    int blocks = maxb < 740 ? maxb : 740;   // 148 SMs x 5 CTAs: full residency
    aploss_fused_kernel<<<blocks, 256>>>(logits, targets, n, out);
}